// round 11
// baseline (speedup 1.0000x reference)
#include <cuda_runtime.h>
#include <cstdint>

// Problem constants (x = [4096, 8192, 1] f32, G = 7)
constexpr int B_ROWS = 4096;
constexpr int I_COLS = 8192;
constexpr int G      = 7;

constexpr int BT    = 512;   // threads per block, 3 CTAs/SM
constexpr int NW    = 16;    // warps
constexpr int NB    = 640;   // quantile buckets (mean ~12.8)
constexpr int NPAIR = NB / 2;
constexpr int CAP   = 24;    // slot capacity per bucket

// per-row global overflow scratch (rare path; worst case one bucket = row)
__device__ uint32_t g_ovf[(size_t)B_ROWS * I_COLS];

// ---- dynamic shared memory layout (~67.7 KB -> 3 CTAs/SM) ----
constexpr size_t OFF_SLOT = 0;                                 // u32 slots[NB*CAP] 61440
constexpr size_t OFF_CNT  = OFF_SLOT + (size_t)NB * CAP * 4;   // u32 cnt[NB]       2560
constexpr size_t OFF_U    = OFF_CNT  + NB * 4;                 // u32 U[NB]         2560
constexpr size_t OFF_BASE = OFF_U    + NB * 4;                 // u32 base[NB+1]
constexpr size_t OFF_AUX  = OFF_BASE + (NB + 1) * 4;           // u32 aux[16]
constexpr size_t OFF_OVFN = OFF_AUX  + 64;                     // u32 ovfn
constexpr size_t OFF_SCAL = OFF_OVFN + 16;                     // f32 scal[32]
constexpr size_t SMEM_BYTES = OFF_SCAL + 128;

// key transform: ascending u32 == descending float
__device__ __forceinline__ uint32_t kd(float f) {
    uint32_t b = __float_as_uint(f);
    uint32_t m = (uint32_t)(((int32_t)b) >> 31) | 0x80000000u;
    return ~(b ^ m);
}
__device__ __forceinline__ float inv_kd(uint32_t k) {
    uint32_t u = ~k;
    return __uint_as_float((u & 0x80000000u) ? (u ^ 0x80000000u) : ~u);
}

// bucket of x: MUFU-based guess from the sigmoid fit of Phi(x), corrected by
// an exact, monotone table walk (correctness depends only on the compares).
__device__ __forceinline__ int bucket_of(float x, uint32_t u, const uint32_t* __restrict__ U) {
    float z = fmaf(0.07056f * x * x, x, 1.5976f * x);
    int b = (int)((float)NB * __frcp_rn(1.0f + __expf(z)));   // ~ NB*(1-Phi(x))
    b = max(0, min(NB - 1, b));
    while (b < NB - 1 && u >= U[b]) ++b;
    while (b > 0 && u < U[b - 1]) --b;
    return b;
}

__device__ __forceinline__ void emit_packed(
    int gr, uint32_t idx, uint32_t off, uint32_t lo,
    float* __restrict__ si, float* s_top, float* s_bot)
{
    si[gr] = (float)idx;
    if (gr < G || gr >= I_COLS - G) {
        float fv = inv_kd(lo + off);
        if (gr < G) s_top[gr] = fv;
        else        s_bot[gr - (I_COLS - G)] = fv;
    }
}
__device__ __forceinline__ void emit_val(
    int gr, uint32_t idx, float val,
    float* __restrict__ si, float* s_top, float* s_bot)
{
    si[gr] = (float)idx;
    if (gr < G)                s_top[gr] = val;
    else if (gr >= I_COLS - G) s_bot[gr - (I_COLS - G)] = val;
}

// ---- 16-wide sub-warp sort: two narrow buckets per warp ----
__device__ __forceinline__ void sort16_u32(
    const uint32_t* __restrict__ sb, int size, int gbase, uint32_t lo,
    int m, float* __restrict__ si, float* s_top, float* s_bot)
{
    uint32_t v = (m < size) ? sb[m] : 0xFFFFFFFFu;
    #pragma unroll
    for (int k = 2; k <= 16; k <<= 1) {
        #pragma unroll
        for (int j = k >> 1; j > 0; j >>= 1) {
            uint32_t w = __shfl_xor_sync(0xFFFFFFFFu, v, j, 16);
            const bool up = ((m & k) == 0);
            const bool keep_lo = (((m & j) == 0) == up);
            v = keep_lo ? min(v, w) : max(v, w);
        }
    }
    if (m < size) emit_packed(gbase + m, v & 8191u, v >> 13, lo, si, s_top, s_bot);
}

// ---- 32-wide narrow bucket (size <= CAP <= 32), u32 payload ----
__device__ __forceinline__ void sort_bucket_u32(
    const uint32_t* __restrict__ sb, int size, int gbase, uint32_t lo,
    int lane, float* __restrict__ si, float* s_top, float* s_bot)
{
    uint32_t v = (lane < size) ? sb[lane] : 0xFFFFFFFFu;
    #pragma unroll
    for (int k = 2; k <= 32; k <<= 1) {
        #pragma unroll
        for (int j = k >> 1; j > 0; j >>= 1) {
            uint32_t w = __shfl_xor_sync(0xFFFFFFFFu, v, j);
            const bool up = ((lane & k) == 0);
            const bool keep_lo = (((lane & j) == 0) == up);
            v = keep_lo ? min(v, w) : max(v, w);
        }
    }
    if (lane < size) emit_packed(gbase + lane, v & 8191u, v >> 13, lo, si, s_top, s_bot);
}

// ---- wide bucket (size <= CAP): slots hold idx; rebuild 45-bit key ----
__device__ __forceinline__ void sort_bucket_wide(
    const uint32_t* __restrict__ sb, int size, int gbase,
    const float* __restrict__ xr, int lane,
    float* __restrict__ si, float* s_top, float* s_bot)
{
    unsigned long long v = ~0ull;
    if (lane < size) {
        uint32_t idx = sb[lane];
        v = ((unsigned long long)kd(xr[idx]) << 13) | idx;
    }
    #pragma unroll
    for (int k = 2; k <= 32; k <<= 1) {
        #pragma unroll
        for (int j = k >> 1; j > 0; j >>= 1) {
            unsigned long long w = __shfl_xor_sync(0xFFFFFFFFu, v, j);
            const bool up = ((lane & k) == 0);
            const bool keep_lo = (((lane & j) == 0) == up);
            v = keep_lo ? (v < w ? v : w) : (v > w ? v : w);
        }
    }
    if (lane < size)
        emit_val(gbase + lane, (uint32_t)(v & 8191u), inv_kd((uint32_t)(v >> 13)),
                 si, s_top, s_bot);
}

// ---- unconditional-correctness fallback for overflowed buckets (rare) ----
__device__ __noinline__ void bucket_fallback(
    const uint32_t* __restrict__ sb, int size, int gbase, int b, bool narrow,
    const uint32_t* __restrict__ ovf, int ovfTotal,
    const float* __restrict__ xr, int lane,
    float* __restrict__ si, float* s_top, float* s_bot)
{
    const int n0 = min(size, CAP);
    auto rank_of = [&](unsigned long long me) -> int {
        int r = 0;
        for (int t = 0; t < n0; t++) {
            uint32_t p2 = sb[t];
            uint32_t i2 = narrow ? (p2 & 8191u) : p2;
            unsigned long long k2 = ((unsigned long long)kd(xr[i2]) << 13) | i2;
            r += (k2 < me);
        }
        for (int j = 0; j < ovfTotal; j++) {
            uint32_t o = ovf[j];
            if ((int)(o >> 13) == b) {
                uint32_t i2 = o & 8191u;
                unsigned long long k2 = ((unsigned long long)kd(xr[i2]) << 13) | i2;
                r += (k2 < me);
            }
        }
        return r;
    };
    if (lane < n0) {
        uint32_t pay = sb[lane];
        uint32_t idx = narrow ? (pay & 8191u) : pay;
        float xv = xr[idx];
        unsigned long long me = ((unsigned long long)kd(xv) << 13) | idx;
        emit_val(gbase + rank_of(me), idx, xv, si, s_top, s_bot);
    }
    for (int j = lane; j < ovfTotal; j += 32) {
        uint32_t o = ovf[j];
        if ((int)(o >> 13) == b) {
            uint32_t idx = o & 8191u;
            float xv = xr[idx];
            unsigned long long me = ((unsigned long long)kd(xv) << 13) | idx;
            emit_val(gbase + rank_of(me), idx, xv, si, s_top, s_bot);
        }
    }
}

extern __shared__ unsigned char smem_raw[];

__global__ void __launch_bounds__(BT, 3)
portfolio_slot3_kernel(const float* __restrict__ x, float* __restrict__ out)
{
    uint32_t* slots = (uint32_t*)(smem_raw + OFF_SLOT);
    uint32_t* cnt   = (uint32_t*)(smem_raw + OFF_CNT);
    uint32_t* U     = (uint32_t*)(smem_raw + OFF_U);
    uint32_t* base  = (uint32_t*)(smem_raw + OFF_BASE);
    uint32_t* aux   = (uint32_t*)(smem_raw + OFF_AUX);
    uint32_t* ovfn  = (uint32_t*)(smem_raw + OFF_OVFN);
    float*    s_top = (float*)(smem_raw + OFF_SCAL);   // [7]
    float*    s_bot = s_top + 8;                       // [7]
    float*    s_win = s_top + 16;                      // [7]
    float*    s_los = s_top + 24;                      // [7]

    const int tid  = threadIdx.x;
    const int wid  = tid >> 5;
    const int lane = tid & 31;
    const int row  = blockIdx.x;
    const float*  xr  = x + (size_t)row * I_COLS;
    const float4* xr4 = (const float4*)xr;
    uint32_t* ovf = g_ovf + (size_t)row * I_COLS;      // per-row overflow scratch

    // ---- init: monotone splitter table + zero counters ----
    for (int i = tid; i < NB - 1; i += BT) {
        float pi = (float)(i + 1) * (1.0f / (float)NB);
        float q  = 0.58754f * __logf((1.0f - pi) / pi);
        U[i] = kd(q);
    }
    if (tid == 0) { U[NB - 1] = 0xFFFFFFFFu; base[NB] = I_COLS; ovfn[0] = 0; }
    for (int i = tid; i < NB; i += BT) cnt[i] = 0;
    __syncthreads();

    // ---- Phase 1 (single pass): bucket + 1-atomic slot scatter ----
    #pragma unroll
    for (int q4 = 0; q4 < 4; q4++) {
        int vi = tid + q4 * BT;
        float4 xv = xr4[vi];
        int e = vi * 4;
        float vals[4] = {xv.x, xv.y, xv.z, xv.w};
        #pragma unroll
        for (int c = 0; c < 4; c++) {
            float f = vals[c];
            uint32_t u = kd(f);
            int b = bucket_of(f, u, U);
            uint32_t lo = b ? U[b - 1] : 0u;
            bool narrow = (U[b] - lo) <= (1u << 19);
            uint32_t idx = (uint32_t)(e + c);
            uint32_t payload = narrow ? (((u - lo) << 13) | idx) : idx;
            uint32_t pos = atomicAdd(&cnt[b], 1u);
            if (pos < CAP) slots[b * CAP + pos] = payload;
            else           ovf[atomicAdd(ovfn, 1u)] = ((uint32_t)b << 13) | idx;
        }
    }
    __syncthreads();

    // ---- Phase 2: exclusive scan of true sizes (cnt preserved) ----
    {
        uint32_t c0 = 0, c1 = 0;
        if (tid < NPAIR) { c0 = cnt[2 * tid]; c1 = cnt[2 * tid + 1]; }
        uint32_t tsum = c0 + c1;
        uint32_t inc = tsum;
        #pragma unroll
        for (int o = 1; o < 32; o <<= 1) {
            uint32_t n = __shfl_up_sync(0xFFFFFFFFu, inc, o);
            if (lane >= o) inc += n;
        }
        if (lane == 31) aux[wid] = inc;
        __syncthreads();
        if (wid == 0) {
            uint32_t v  = (lane < NW) ? aux[lane] : 0;
            uint32_t vi = v;
            #pragma unroll
            for (int o = 1; o < 32; o <<= 1) {
                uint32_t n = __shfl_up_sync(0xFFFFFFFFu, vi, o);
                if (lane >= o) vi += n;
            }
            if (lane < NW) aux[lane] = vi - v;       // exclusive warp prefix
        }
        __syncthreads();
        if (tid < NPAIR) {
            uint32_t excl = aux[wid] + (inc - tsum);
            base[2 * tid] = excl;
            base[2 * tid + 1] = excl + c0;
        }
    }
    __syncthreads();

    // ---- b_c zero fill (independent; overlaps with sorts) ----
    float* bc = out + (size_t)row * I_COLS;
    float* si = out + (size_t)B_ROWS * I_COLS + (size_t)row * I_COLS;
    {
        float4 z = make_float4(0.f, 0.f, 0.f, 0.f);
        float4* bc4 = (float4*)bc;
        #pragma unroll
        for (int q4 = 0; q4 < 4; q4++) bc4[tid + q4 * BT] = z;
    }

    // ---- Phase 4: per-warp register sorts (two buckets per warp if small) ----
    const int ovfTotal = (int)ovfn[0];
    for (int pb = wid; pb < NPAIR; pb += NW) {
        int b0 = 2 * pb, b1 = b0 + 1;
        int s0 = (int)cnt[b0], s1 = (int)cnt[b1];
        int g0 = (int)base[b0], g1 = (int)base[b1];
        uint32_t lo0 = b0 ? U[b0 - 1] : 0u;
        uint32_t lo1 = U[b0];
        bool nar0 = (U[b0] - lo0) <= (1u << 19);
        bool nar1 = (U[b1] - lo1) <= (1u << 19);
        if (s0 <= 16 && s1 <= 16 && nar0 && nar1) {
            const int half = lane >> 4, m = lane & 15;
            sort16_u32(slots + (half ? b1 : b0) * CAP, half ? s1 : s0,
                       half ? g1 : g0, half ? lo1 : lo0, m, si, s_top, s_bot);
        } else {
            if (s0 > 0) {
                if (s0 <= CAP) {
                    if (nar0) sort_bucket_u32(slots + b0 * CAP, s0, g0, lo0, lane, si, s_top, s_bot);
                    else      sort_bucket_wide(slots + b0 * CAP, s0, g0, xr, lane, si, s_top, s_bot);
                } else bucket_fallback(slots + b0 * CAP, s0, g0, b0, nar0, ovf, ovfTotal, xr, lane, si, s_top, s_bot);
            }
            if (s1 > 0) {
                if (s1 <= CAP) {
                    if (nar1) sort_bucket_u32(slots + b1 * CAP, s1, g1, lo1, lane, si, s_top, s_bot);
                    else      sort_bucket_wide(slots + b1 * CAP, s1, g1, xr, lane, si, s_top, s_bot);
                } else bucket_fallback(slots + b1 * CAP, s1, g1, b1, nar1, ovf, ovfTotal, xr, lane, si, s_top, s_bot);
            }
        }
    }
    __syncthreads();

    // ---- softmaxes ----
    if (tid == 0) {
        float m = s_top[0];
        #pragma unroll
        for (int i = 1; i < G; i++) m = fmaxf(m, s_top[i]);
        float e[G], s = 0.0f;
        #pragma unroll
        for (int i = 0; i < G; i++) { e[i] = expf(s_top[i] - m); s += e[i]; }
        float inv = 1.0f / s;
        #pragma unroll
        for (int i = 0; i < G; i++) s_win[i] = e[i] * inv;

        float m2 = 1.0f - s_bot[0];
        #pragma unroll
        for (int i = 1; i < G; i++) m2 = fmaxf(m2, 1.0f - s_bot[i]);
        float e2[G], s2 = 0.0f;
        #pragma unroll
        for (int i = 0; i < G; i++) { e2[i] = expf((1.0f - s_bot[i]) - m2); s2 += e2[i]; }
        float inv2 = 1.0f / s2;
        #pragma unroll
        for (int i = 0; i < G; i++) s_los[i] = -e2[i] * inv2;
    }
    __syncthreads();

    if (tid < G)          bc[tid] = s_win[tid];
    else if (tid < 2 * G) bc[I_COLS - G + (tid - G)] = s_los[tid - G];
}

extern "C" void kernel_launch(void* const* d_in, const int* in_sizes, int n_in,
                              void* d_out, int out_size)
{
    (void)in_sizes; (void)n_in; (void)out_size;
    const float* x = (const float*)d_in[0];
    float* out = (float*)d_out;

    cudaFuncSetAttribute(portfolio_slot3_kernel,
                         cudaFuncAttributeMaxDynamicSharedMemorySize,
                         (int)SMEM_BYTES);
    portfolio_slot3_kernel<<<B_ROWS, BT, SMEM_BYTES>>>(x, out);
}

// round 14
// speedup vs baseline: 1.0250x; 1.0250x over previous
#include <cuda_runtime.h>
#include <cstdint>

// Problem constants (x = [4096, 8192, 1] f32, G = 7)
constexpr int B_ROWS = 4096;
constexpr int I_COLS = 8192;
constexpr int G      = 7;

constexpr int BT    = 512;   // threads per block, 3 CTAs/SM
constexpr int NW    = 16;    // warps
constexpr int NB    = 640;   // quantile buckets (mean ~12.8)
constexpr int NPAIR = NB / 2;
constexpr int CAP   = 26;    // slot capacity per bucket

// per-row global overflow scratch (rare path; worst case one bucket = row)
__device__ uint32_t g_ovf[(size_t)B_ROWS * I_COLS];

// ---- dynamic shared memory layout (~72.7 KB -> 3 CTAs/SM) ----
constexpr size_t OFF_SLOT = 0;                                 // u32 slots[NB*CAP] 66560
constexpr size_t OFF_CNT  = OFF_SLOT + (size_t)NB * CAP * 4;   // u32 cnt[NB]
constexpr size_t OFF_U    = OFF_CNT  + NB * 4;                 // u32 U[NB]
constexpr size_t OFF_BASE = OFF_U    + NB * 4;                 // u32 base[NB+1]
constexpr size_t OFF_AUX  = OFF_BASE + (NB + 1) * 4;           // u32 aux[16]
constexpr size_t OFF_OVFN = OFF_AUX  + 64;                     // u32 ovfn
constexpr size_t OFF_SCAL = OFF_OVFN + 16;                     // f32 scal[32]
constexpr size_t SMEM_BYTES = OFF_SCAL + 128;

// key transform: ascending u32 == descending float
__device__ __forceinline__ uint32_t kd(float f) {
    uint32_t b = __float_as_uint(f);
    uint32_t m = (uint32_t)(((int32_t)b) >> 31) | 0x80000000u;
    return ~(b ^ m);
}
__device__ __forceinline__ float inv_kd(uint32_t k) {
    uint32_t u = ~k;
    return __uint_as_float((u & 0x80000000u) ? (u ^ 0x80000000u) : ~u);
}

// bucket of x: MUFU-based guess from the sigmoid fit of Phi(x), corrected by
// an exact, monotone table walk (correctness depends only on the compares).
__device__ __forceinline__ int bucket_of(float x, uint32_t u, const uint32_t* __restrict__ U) {
    float z = fmaf(0.07056f * x * x, x, 1.5976f * x);
    int b = (int)((float)NB * __frcp_rn(1.0f + __expf(z)));   // ~ NB*(1-Phi(x))
    b = max(0, min(NB - 1, b));
    while (b < NB - 1 && u >= U[b]) ++b;
    while (b > 0 && u < U[b - 1]) --b;
    return b;
}

__device__ __forceinline__ void emit_packed(
    int gr, uint32_t idx, uint32_t off, uint32_t lo,
    float* __restrict__ si, float* s_top, float* s_bot)
{
    si[gr] = (float)idx;
    if (gr < G || gr >= I_COLS - G) {
        float fv = inv_kd(lo + off);
        if (gr < G) s_top[gr] = fv;
        else        s_bot[gr - (I_COLS - G)] = fv;
    }
}
__device__ __forceinline__ void emit_val(
    int gr, uint32_t idx, float val,
    float* __restrict__ si, float* s_top, float* s_bot)
{
    si[gr] = (float)idx;
    if (gr < G)                s_top[gr] = val;
    else if (gr >= I_COLS - G) s_bot[gr - (I_COLS - G)] = val;
}

// ---- 16-wide sub-warp sort: two narrow buckets per warp (HOT, inline) ----
__device__ __forceinline__ void sort16_u32(
    const uint32_t* __restrict__ sb, int size, int gbase, uint32_t lo,
    int m, float* __restrict__ si, float* s_top, float* s_bot)
{
    uint32_t v = (m < size) ? sb[m] : 0xFFFFFFFFu;
    #pragma unroll
    for (int k = 2; k <= 16; k <<= 1) {
        #pragma unroll
        for (int j = k >> 1; j > 0; j >>= 1) {
            uint32_t w = __shfl_xor_sync(0xFFFFFFFFu, v, j, 16);
            const bool up = ((m & k) == 0);
            const bool keep_lo = (((m & j) == 0) == up);
            v = keep_lo ? min(v, w) : max(v, w);
        }
    }
    if (m < size) emit_packed(gbase + m, v & 8191u, v >> 13, lo, si, s_top, s_bot);
}

// ---- 32-wide narrow bucket (size <= CAP <= 32), u32 payload ----
__device__ __forceinline__ void sort_bucket_u32(
    const uint32_t* __restrict__ sb, int size, int gbase, uint32_t lo,
    int lane, float* __restrict__ si, float* s_top, float* s_bot)
{
    uint32_t v = (lane < size) ? sb[lane] : 0xFFFFFFFFu;
    #pragma unroll
    for (int k = 2; k <= 32; k <<= 1) {
        #pragma unroll
        for (int j = k >> 1; j > 0; j >>= 1) {
            uint32_t w = __shfl_xor_sync(0xFFFFFFFFu, v, j);
            const bool up = ((lane & k) == 0);
            const bool keep_lo = (((lane & j) == 0) == up);
            v = keep_lo ? min(v, w) : max(v, w);
        }
    }
    if (lane < size) emit_packed(gbase + lane, v & 8191u, v >> 13, lo, si, s_top, s_bot);
}

// ---- wide bucket (size <= CAP): slots hold idx; rebuild 45-bit key (COLD) ----
__device__ __noinline__ void sort_bucket_wide(
    const uint32_t* __restrict__ sb, int size, int gbase,
    const float* __restrict__ xr, int lane,
    float* __restrict__ si, float* s_top, float* s_bot)
{
    unsigned long long v = ~0ull;
    if (lane < size) {
        uint32_t idx = sb[lane];
        v = ((unsigned long long)kd(xr[idx]) << 13) | idx;
    }
    #pragma unroll
    for (int k = 2; k <= 32; k <<= 1) {
        #pragma unroll
        for (int j = k >> 1; j > 0; j >>= 1) {
            unsigned long long w = __shfl_xor_sync(0xFFFFFFFFu, v, j);
            const bool up = ((lane & k) == 0);
            const bool keep_lo = (((lane & j) == 0) == up);
            v = keep_lo ? (v < w ? v : w) : (v > w ? v : w);
        }
    }
    if (lane < size)
        emit_val(gbase + lane, (uint32_t)(v & 8191u), inv_kd((uint32_t)(v >> 13)),
                 si, s_top, s_bot);
}

// ---- unconditional-correctness fallback for overflowed buckets (COLD) ----
__device__ __noinline__ void bucket_fallback(
    const uint32_t* __restrict__ sb, int size, int gbase, int b, bool narrow,
    const uint32_t* __restrict__ ovf, int ovfTotal,
    const float* __restrict__ xr, int lane,
    float* __restrict__ si, float* s_top, float* s_bot)
{
    const int n0 = min(size, CAP);
    auto rank_of = [&](unsigned long long me) -> int {
        int r = 0;
        for (int t = 0; t < n0; t++) {
            uint32_t p2 = sb[t];
            uint32_t i2 = narrow ? (p2 & 8191u) : p2;
            unsigned long long k2 = ((unsigned long long)kd(xr[i2]) << 13) | i2;
            r += (k2 < me);
        }
        for (int j = 0; j < ovfTotal; j++) {
            uint32_t o = ovf[j];
            if ((int)(o >> 13) == b) {
                uint32_t i2 = o & 8191u;
                unsigned long long k2 = ((unsigned long long)kd(xr[i2]) << 13) | i2;
                r += (k2 < me);
            }
        }
        return r;
    };
    if (lane < n0) {
        uint32_t pay = sb[lane];
        uint32_t idx = narrow ? (pay & 8191u) : pay;
        float xv = xr[idx];
        unsigned long long me = ((unsigned long long)kd(xv) << 13) | idx;
        emit_val(gbase + rank_of(me), idx, xv, si, s_top, s_bot);
    }
    for (int j = lane; j < ovfTotal; j += 32) {
        uint32_t o = ovf[j];
        if ((int)(o >> 13) == b) {
            uint32_t idx = o & 8191u;
            float xv = xr[idx];
            unsigned long long me = ((unsigned long long)kd(xv) << 13) | idx;
            emit_val(gbase + rank_of(me), idx, xv, si, s_top, s_bot);
        }
    }
}

// ---- COLD dispatcher for every non-pair16 bucket (keeps hot loop lean) ----
__device__ __noinline__ void process_slow(
    const uint32_t* __restrict__ slots, const uint32_t* __restrict__ U,
    int b, int size, int gbase,
    const uint32_t* __restrict__ ovf, int ovfTotal,
    const float* __restrict__ xr, int lane,
    float* __restrict__ si, float* s_top, float* s_bot)
{
    if (size <= 0) return;
    uint32_t lo = b ? U[b - 1] : 0u;
    bool narrow = (U[b] - lo) <= (1u << 19);
    const uint32_t* sb = slots + b * CAP;
    if (size <= CAP) {
        if (narrow) sort_bucket_u32(sb, size, gbase, lo, lane, si, s_top, s_bot);
        else        sort_bucket_wide(sb, size, gbase, xr, lane, si, s_top, s_bot);
    } else {
        bucket_fallback(sb, size, gbase, b, narrow, ovf, ovfTotal, xr, lane, si, s_top, s_bot);
    }
}

extern __shared__ unsigned char smem_raw[];

__global__ void __launch_bounds__(BT, 3)
portfolio_slot4_kernel(const float* __restrict__ x, float* __restrict__ out)
{
    uint32_t* slots = (uint32_t*)(smem_raw + OFF_SLOT);
    uint32_t* cnt   = (uint32_t*)(smem_raw + OFF_CNT);
    uint32_t* U     = (uint32_t*)(smem_raw + OFF_U);
    uint32_t* base  = (uint32_t*)(smem_raw + OFF_BASE);
    uint32_t* aux   = (uint32_t*)(smem_raw + OFF_AUX);
    uint32_t* ovfn  = (uint32_t*)(smem_raw + OFF_OVFN);
    float*    s_top = (float*)(smem_raw + OFF_SCAL);   // [7]
    float*    s_bot = s_top + 8;                       // [7]
    float*    s_win = s_top + 16;                      // [7]
    float*    s_los = s_top + 24;                      // [7]

    const int tid  = threadIdx.x;
    const int wid  = tid >> 5;
    const int lane = tid & 31;
    const int row  = blockIdx.x;
    const float*  xr  = x + (size_t)row * I_COLS;
    const float4* xr4 = (const float4*)xr;
    uint32_t* ovf = g_ovf + (size_t)row * I_COLS;      // per-row overflow scratch

    // ---- init: monotone splitter table + zero counters ----
    for (int i = tid; i < NB - 1; i += BT) {
        float pi = (float)(i + 1) * (1.0f / (float)NB);
        float q  = 0.58754f * __logf((1.0f - pi) / pi);
        U[i] = kd(q);
    }
    if (tid == 0) { U[NB - 1] = 0xFFFFFFFFu; base[NB] = I_COLS; ovfn[0] = 0; }
    for (int i = tid; i < NB; i += BT) cnt[i] = 0;
    __syncthreads();

    // ---- Phase 1 (single pass): bucket + 1-atomic slot scatter ----
    #pragma unroll
    for (int q4 = 0; q4 < 4; q4++) {
        int vi = tid + q4 * BT;
        float4 xv = xr4[vi];
        int e = vi * 4;
        #pragma unroll
        for (int c = 0; c < 4; c++) {
            float f = (c == 0) ? xv.x : (c == 1) ? xv.y : (c == 2) ? xv.z : xv.w;
            uint32_t u = kd(f);
            int b = bucket_of(f, u, U);
            uint32_t lo = b ? U[b - 1] : 0u;
            bool narrow = (U[b] - lo) <= (1u << 19);
            uint32_t idx = (uint32_t)(e + c);
            uint32_t payload = narrow ? (((u - lo) << 13) | idx) : idx;
            uint32_t pos = atomicAdd(&cnt[b], 1u);
            if (pos < CAP) slots[b * CAP + pos] = payload;
            else           ovf[atomicAdd(ovfn, 1u)] = ((uint32_t)b << 13) | idx;
        }
    }
    __syncthreads();

    // ---- Phase 2: exclusive scan of true sizes (cnt preserved) ----
    {
        uint32_t c0 = 0, c1 = 0;
        if (tid < NPAIR) { c0 = cnt[2 * tid]; c1 = cnt[2 * tid + 1]; }
        uint32_t tsum = c0 + c1;
        uint32_t inc = tsum;
        #pragma unroll
        for (int o = 1; o < 32; o <<= 1) {
            uint32_t n = __shfl_up_sync(0xFFFFFFFFu, inc, o);
            if (lane >= o) inc += n;
        }
        if (lane == 31) aux[wid] = inc;
        __syncthreads();
        if (wid == 0) {
            uint32_t v  = (lane < NW) ? aux[lane] : 0;
            uint32_t vi = v;
            #pragma unroll
            for (int o = 1; o < 32; o <<= 1) {
                uint32_t n = __shfl_up_sync(0xFFFFFFFFu, vi, o);
                if (lane >= o) vi += n;
            }
            if (lane < NW) aux[lane] = vi - v;       // exclusive warp prefix
        }
        __syncthreads();
        if (tid < NPAIR) {
            uint32_t excl = aux[wid] + (inc - tsum);
            base[2 * tid] = excl;
            base[2 * tid + 1] = excl + c0;
        }
    }
    __syncthreads();

    // ---- b_c zero fill (independent; overlaps with sorts) ----
    float* bc = out + (size_t)row * I_COLS;
    float* si = out + (size_t)B_ROWS * I_COLS + (size_t)row * I_COLS;
    {
        float4 z = make_float4(0.f, 0.f, 0.f, 0.f);
        float4* bc4 = (float4*)bc;
        #pragma unroll
        for (int q4 = 0; q4 < 4; q4++) bc4[tid + q4 * BT] = z;
    }

    // ---- Phase 4: pair16 hot path inline; everything else via cold call ----
    const int ovfTotal = (int)ovfn[0];
    for (int pb = wid; pb < NPAIR; pb += NW) {
        int b0 = 2 * pb, b1 = b0 + 1;
        int s0 = (int)cnt[b0], s1 = (int)cnt[b1];
        int g0 = (int)base[b0], g1 = (int)base[b1];
        uint32_t lo0 = b0 ? U[b0 - 1] : 0u;
        uint32_t lo1 = U[b0];
        bool nar0 = (U[b0] - lo0) <= (1u << 19);
        bool nar1 = (U[b1] - lo1) <= (1u << 19);
        if (s0 <= 16 && s1 <= 16 && nar0 && nar1) {
            const int half = lane >> 4, m = lane & 15;
            sort16_u32(slots + (half ? b1 : b0) * CAP, half ? s1 : s0,
                       half ? g1 : g0, half ? lo1 : lo0, m, si, s_top, s_bot);
        } else {
            process_slow(slots, U, b0, s0, g0, ovf, ovfTotal, xr, lane, si, s_top, s_bot);
            process_slow(slots, U, b1, s1, g1, ovf, ovfTotal, xr, lane, si, s_top, s_bot);
        }
    }
    __syncthreads();

    // ---- softmaxes ----
    if (tid == 0) {
        float m = s_top[0];
        #pragma unroll
        for (int i = 1; i < G; i++) m = fmaxf(m, s_top[i]);
        float e[G], s = 0.0f;
        #pragma unroll
        for (int i = 0; i < G; i++) { e[i] = expf(s_top[i] - m); s += e[i]; }
        float inv = 1.0f / s;
        #pragma unroll
        for (int i = 0; i < G; i++) s_win[i] = e[i] * inv;

        float m2 = 1.0f - s_bot[0];
        #pragma unroll
        for (int i = 1; i < G; i++) m2 = fmaxf(m2, 1.0f - s_bot[i]);
        float e2[G], s2 = 0.0f;
        #pragma unroll
        for (int i = 0; i < G; i++) { e2[i] = expf((1.0f - s_bot[i]) - m2); s2 += e2[i]; }
        float inv2 = 1.0f / s2;
        #pragma unroll
        for (int i = 0; i < G; i++) s_los[i] = -e2[i] * inv2;
    }
    __syncthreads();

    if (tid < G)          bc[tid] = s_win[tid];
    else if (tid < 2 * G) bc[I_COLS - G + (tid - G)] = s_los[tid - G];
}

extern "C" void kernel_launch(void* const* d_in, const int* in_sizes, int n_in,
                              void* d_out, int out_size)
{
    (void)in_sizes; (void)n_in; (void)out_size;
    const float* x = (const float*)d_in[0];
    float* out = (float*)d_out;

    cudaFuncSetAttribute(portfolio_slot4_kernel,
                         cudaFuncAttributeMaxDynamicSharedMemorySize,
                         (int)SMEM_BYTES);
    portfolio_slot4_kernel<<<B_ROWS, BT, SMEM_BYTES>>>(x, out);
}

// round 15
// speedup vs baseline: 1.1318x; 1.1042x over previous
#include <cuda_runtime.h>
#include <cstdint>

// Problem constants (x = [4096, 8192, 1] f32, G = 7)
constexpr int B_ROWS = 4096;
constexpr int I_COLS = 8192;
constexpr int G      = 7;

constexpr int BT    = 512;   // threads per block, 3 CTAs/SM
constexpr int NW    = 16;    // warps
constexpr int NB    = 768;   // quantile buckets (mean ~10.7)
constexpr int NPAIR = NB / 2;

// ---- dynamic shared memory layout (~71.7 KB -> 3 CTAs/SM) ----
constexpr size_t OFF_BUF  = 0;                       // u64 buf[8192] (also id-cache) 65536
constexpr size_t OFF_HIST = OFF_BUF + 65536;         // u32 histPk[NPAIR] (2x u16)    1536
constexpr size_t OFF_CUR  = OFF_HIST + NPAIR * 4;    // u32 curPk[NPAIR]  (2x u16)    1536
constexpr size_t OFF_BASE = OFF_CUR + NPAIR * 4;     // u16 base16[NB+2]              1540->1544
constexpr size_t OFF_U    = OFF_BASE + 1544;         // u32 U[NB]                     3072
constexpr size_t OFF_AUX  = OFF_U + NB * 4;          // u32 aux[16]
constexpr size_t OFF_SCAL = OFF_AUX + 64;            // f32 scal[32]
constexpr size_t SMEM_BYTES = OFF_SCAL + 128;

// key transform: ascending u32 == descending float
__device__ __forceinline__ uint32_t kd(float f) {
    uint32_t b = __float_as_uint(f);
    uint32_t m = (uint32_t)(((int32_t)b) >> 31) | 0x80000000u;
    return ~(b ^ m);
}
__device__ __forceinline__ float inv_kd(uint32_t k) {
    uint32_t u = ~k;
    return __uint_as_float((u & 0x80000000u) ? (u ^ 0x80000000u) : ~u);
}

// bucket of x: MUFU-based guess from the sigmoid fit of Phi(x), corrected by
// an exact, monotone table walk (correctness depends only on the compares).
__device__ __forceinline__ int bucket_of(float x, uint32_t u, const uint32_t* __restrict__ U) {
    float z = fmaf(0.07056f * x * x, x, 1.5976f * x);
    int b = (int)((float)NB * __frcp_rn(1.0f + __expf(z)));   // ~ NB*(1-Phi(x))
    b = max(0, min(NB - 1, b));
    while (b < NB - 1 && u >= U[b]) ++b;
    while (b > 0 && u < U[b - 1]) --b;
    return b;
}

// ---------------- warp-register bitonic sorts (ascending) ----------------
template <int R>
__device__ __forceinline__ void bitonic32(uint32_t v[R], int lane) {
    constexpr int N = R * 32;
    #pragma unroll
    for (int k = 2; k <= N; k <<= 1) {
        #pragma unroll
        for (int j = k >> 1; j > 0; j >>= 1) {
            if (j >= 32) {
                const int jr = j >> 5;
                #pragma unroll
                for (int r = 0; r < R; r++) {
                    if ((r & jr) == 0) {
                        const int r2 = r + jr;
                        const int e  = r * 32 + lane;
                        const bool up = ((e & k) == 0);
                        uint32_t a = v[r], b = v[r2];
                        uint32_t lo = min(a, b), hi = max(a, b);
                        v[r]  = up ? lo : hi;
                        v[r2] = up ? hi : lo;
                    }
                }
            } else {
                #pragma unroll
                for (int r = 0; r < R; r++) {
                    const int e = r * 32 + lane;
                    uint32_t w = __shfl_xor_sync(0xFFFFFFFFu, v[r], j);
                    const bool up = ((e & k) == 0);
                    const bool keep_lo = (((e & j) == 0) == up);
                    v[r] = keep_lo ? min(v[r], w) : max(v[r], w);
                }
            }
        }
    }
}

template <int R>
__device__ __forceinline__ void bitonic64(unsigned long long v[R], int lane) {
    constexpr int N = R * 32;
    #pragma unroll
    for (int k = 2; k <= N; k <<= 1) {
        #pragma unroll
        for (int j = k >> 1; j > 0; j >>= 1) {
            if (j >= 32) {
                const int jr = j >> 5;
                #pragma unroll
                for (int r = 0; r < R; r++) {
                    if ((r & jr) == 0) {
                        const int r2 = r + jr;
                        const int e  = r * 32 + lane;
                        const bool up = ((e & k) == 0);
                        unsigned long long a = v[r], b = v[r2];
                        unsigned long long lo = a < b ? a : b;
                        unsigned long long hi = a < b ? b : a;
                        v[r]  = up ? lo : hi;
                        v[r2] = up ? hi : lo;
                    }
                }
            } else {
                #pragma unroll
                for (int r = 0; r < R; r++) {
                    const int e = r * 32 + lane;
                    unsigned long long w = __shfl_xor_sync(0xFFFFFFFFu, v[r], j);
                    const bool up = ((e & k) == 0);
                    const bool keep_lo = (((e & j) == 0) == up);
                    v[r] = keep_lo ? (v[r] < w ? v[r] : w) : (v[r] > w ? v[r] : w);
                }
            }
        }
    }
}

__device__ __forceinline__ void emit_packed(
    int gr, uint32_t idx, uint32_t off, uint32_t lo,
    float* __restrict__ si, float* s_top, float* s_bot)
{
    si[gr] = (float)idx;
    if (gr < G || gr >= I_COLS - G) {
        float fv = inv_kd(lo + off);
        if (gr < G) s_top[gr] = fv;
        else        s_bot[gr - (I_COLS - G)] = fv;
    }
}

// ---- 16-wide sub-warp sort: two narrow buckets per warp ----
__device__ __forceinline__ void sort16_u32(
    const unsigned long long* __restrict__ buf, int start, int size, uint32_t lo,
    int m, float* __restrict__ si, float* s_top, float* s_bot)
{
    const unsigned long long sub = (unsigned long long)lo << 13;
    uint32_t v = (m < size) ? (uint32_t)(buf[start + m] - sub) : 0xFFFFFFFFu;
    #pragma unroll
    for (int k = 2; k <= 16; k <<= 1) {
        #pragma unroll
        for (int j = k >> 1; j > 0; j >>= 1) {
            uint32_t w = __shfl_xor_sync(0xFFFFFFFFu, v, j, 16);
            const bool up = ((m & k) == 0);
            const bool keep_lo = (((m & j) == 0) == up);
            v = keep_lo ? min(v, w) : max(v, w);
        }
    }
    if (m < size) emit_packed(start + m, v & 8191u, v >> 13, lo, si, s_top, s_bot);
}

// narrow 32-wide path (u32 payload from u64 buf)
template <int R>
__device__ __forceinline__ void sort_bucket_u32(
    const unsigned long long* __restrict__ buf, int start, int size, uint32_t lo,
    int lane, float* __restrict__ si, float* s_top, float* s_bot)
{
    const unsigned long long sub = (unsigned long long)lo << 13;
    uint32_t v[R];
    #pragma unroll
    for (int r = 0; r < R; r++) {
        int m = r * 32 + lane;
        v[r] = (m < size) ? (uint32_t)(buf[start + m] - sub) : 0xFFFFFFFFu;
    }
    bitonic32<R>(v, lane);
    #pragma unroll
    for (int r = 0; r < R; r++) {
        int m = r * 32 + lane;
        if (m < size) emit_packed(start + m, v[r] & 8191u, v[r] >> 13, lo, si, s_top, s_bot);
    }
}

// wide path: full u64 packed (kd<<13 | idx)
template <int R>
__device__ __forceinline__ void sort_bucket_u64(
    const unsigned long long* __restrict__ buf, int start, int size, int lane,
    float* __restrict__ si, float* s_top, float* s_bot)
{
    unsigned long long v[R];
    #pragma unroll
    for (int r = 0; r < R; r++) {
        int m = r * 32 + lane;
        v[r] = (m < size) ? buf[start + m] : ~0ull;
    }
    bitonic64<R>(v, lane);
    #pragma unroll
    for (int r = 0; r < R; r++) {
        int m = r * 32 + lane;
        if (m < size) {
            unsigned long long p = v[r];
            int gr = start + m;
            si[gr] = (float)(unsigned)(p & 8191u);
            if (gr < G)           s_top[gr] = inv_kd((uint32_t)(p >> 13));
            if (gr >= I_COLS - G) s_bot[gr - (I_COLS - G)] = inv_kd((uint32_t)(p >> 13));
        }
    }
}

extern __shared__ unsigned char smem_raw[];

__global__ void __launch_bounds__(BT, 3)
portfolio_bucket_v5(const float* __restrict__ x, float* __restrict__ out)
{
    unsigned long long* buf    = (unsigned long long*)(smem_raw + OFF_BUF);
    uint32_t*           histPk = (uint32_t*)(smem_raw + OFF_HIST);
    uint32_t*           curPk  = (uint32_t*)(smem_raw + OFF_CUR);
    unsigned short*     base16 = (unsigned short*)(smem_raw + OFF_BASE);
    uint32_t*           U      = (uint32_t*)(smem_raw + OFF_U);
    uint32_t*           aux    = (uint32_t*)(smem_raw + OFF_AUX);
    float*              s_top  = (float*)(smem_raw + OFF_SCAL);   // [7]
    float*              s_bot  = s_top + 8;                       // [7]
    float*              s_win  = s_top + 16;                      // [7]
    float*              s_los  = s_top + 24;                      // [7]

    const int tid  = threadIdx.x;
    const int wid  = tid >> 5;
    const int lane = tid & 31;
    const int row  = blockIdx.x;

    const float*  xr  = x + (size_t)row * I_COLS;
    const float4* xr4 = (const float4*)xr;

    // ---- init: monotone splitter table + zero packed hist ----
    for (int i = tid; i < NB - 1; i += BT) {
        float pi = (float)(i + 1) * (1.0f / (float)NB);
        float q  = 0.58754f * __logf((1.0f - pi) / pi);
        U[i] = kd(q);
    }
    if (tid == 0) { U[NB - 1] = 0xFFFFFFFFu; base16[NB] = (unsigned short)I_COLS; }
    if (tid < NPAIR) histPk[tid] = 0;
    __syncthreads();

    // ---- Phase 1: bucket each element; cache packed ids in (idle) buf;
    //      packed u16 histogram via one u32 atomic per element ----
    #pragma unroll
    for (int q4 = 0; q4 < 4; q4++) {
        int vi = tid + q4 * BT;
        float4 xv = xr4[vi];
        int b0 = bucket_of(xv.x, kd(xv.x), U);
        int b1 = bucket_of(xv.y, kd(xv.y), U);
        int b2 = bucket_of(xv.z, kd(xv.z), U);
        int b3 = bucket_of(xv.w, kd(xv.w), U);
        buf[vi] = (unsigned long long)(uint32_t)(b0 | (b1 << 16))
                | ((unsigned long long)(uint32_t)(b2 | (b3 << 16)) << 32);
        atomicAdd(&histPk[b0 >> 1], 1u << ((b0 & 1) << 4));
        atomicAdd(&histPk[b1 >> 1], 1u << ((b1 & 1) << 4));
        atomicAdd(&histPk[b2 >> 1], 1u << ((b2 & 1) << 4));
        atomicAdd(&histPk[b3 >> 1], 1u << ((b3 & 1) << 4));
    }
    __syncthreads();

    // ---- Phase 2: scan packed pairs -> base16[] and packed cursors ----
    {
        uint32_t pk = 0;
        if (tid < NPAIR) pk = histPk[tid];
        uint32_t c0 = pk & 0xFFFFu, c1 = pk >> 16;
        uint32_t tsum = c0 + c1;
        uint32_t inc = tsum;
        #pragma unroll
        for (int o = 1; o < 32; o <<= 1) {
            uint32_t n = __shfl_up_sync(0xFFFFFFFFu, inc, o);
            if (lane >= o) inc += n;
        }
        if (lane == 31) aux[wid] = inc;
        __syncthreads();
        if (wid == 0) {
            uint32_t v  = (lane < NW) ? aux[lane] : 0;
            uint32_t vi = v;
            #pragma unroll
            for (int o = 1; o < 32; o <<= 1) {
                uint32_t n = __shfl_up_sync(0xFFFFFFFFu, vi, o);
                if (lane >= o) vi += n;
            }
            if (lane < NW) aux[lane] = vi - v;       // exclusive warp prefix
        }
        __syncthreads();
        if (tid < NPAIR) {
            uint32_t excl = aux[wid] + (inc - tsum);
            uint32_t packed = excl | ((excl + c0) << 16);
            ((uint32_t*)base16)[tid] = packed;       // base16[2t], base16[2t+1]
            curPk[tid] = packed;                     // running cursors
        }
    }
    __syncthreads();

    // ---- Phase 3: read cached ids, then scatter packed (kd<<13 | idx) ----
    {
        unsigned long long idw[4];
        #pragma unroll
        for (int q4 = 0; q4 < 4; q4++) idw[q4] = buf[tid + q4 * BT];
        __syncthreads();                             // ids read before overwrite
        #pragma unroll
        for (int q4 = 0; q4 < 4; q4++) {
            int vi = tid + q4 * BT;
            float4 xv = xr4[vi];                     // cache re-hit
            uint32_t k0 = kd(xv.x), k1 = kd(xv.y), k2 = kd(xv.z), k3 = kd(xv.w);
            unsigned long long w = idw[q4];
            int e = vi * 4;
            uint32_t b0 = (uint32_t)w & 0xFFFFu;
            uint32_t sh0 = (b0 & 1) << 4;
            uint32_t p0 = (atomicAdd(&curPk[b0 >> 1], 1u << sh0) >> sh0) & 0xFFFFu;
            buf[p0] = ((unsigned long long)k0 << 13) | (unsigned)(e + 0);
            uint32_t b1 = (uint32_t)(w >> 16) & 0xFFFFu;
            uint32_t sh1 = (b1 & 1) << 4;
            uint32_t p1 = (atomicAdd(&curPk[b1 >> 1], 1u << sh1) >> sh1) & 0xFFFFu;
            buf[p1] = ((unsigned long long)k1 << 13) | (unsigned)(e + 1);
            uint32_t b2 = (uint32_t)(w >> 32) & 0xFFFFu;
            uint32_t sh2 = (b2 & 1) << 4;
            uint32_t p2 = (atomicAdd(&curPk[b2 >> 1], 1u << sh2) >> sh2) & 0xFFFFu;
            buf[p2] = ((unsigned long long)k2 << 13) | (unsigned)(e + 2);
            uint32_t b3 = (uint32_t)(w >> 48) & 0xFFFFu;
            uint32_t sh3 = (b3 & 1) << 4;
            uint32_t p3 = (atomicAdd(&curPk[b3 >> 1], 1u << sh3) >> sh3) & 0xFFFFu;
            buf[p3] = ((unsigned long long)k3 << 13) | (unsigned)(e + 3);
        }
    }
    __syncthreads();

    // ---- b_c zero fill (independent; overlaps with sorts) ----
    float* bc = out + (size_t)row * I_COLS;
    float* si = out + (size_t)B_ROWS * I_COLS + (size_t)row * I_COLS;
    {
        float4 z = make_float4(0.f, 0.f, 0.f, 0.f);
        float4* bc4 = (float4*)bc;
        #pragma unroll
        for (int q4 = 0; q4 < 4; q4++) bc4[tid + q4 * BT] = z;
    }

    // ---- Phase 4: two buckets per warp (16-wide nets) where possible ----
    for (int pb = wid; pb < NPAIR; pb += NW) {
        int b0 = 2 * pb, b1 = b0 + 1;
        uint32_t pk = histPk[pb];                    // counts preserved
        int s0 = (int)(pk & 0xFFFFu), s1 = (int)(pk >> 16);
        uint32_t gpk = ((const uint32_t*)base16)[pb];
        int g0 = (int)(gpk & 0xFFFFu), g1 = (int)(gpk >> 16);
        uint32_t lo0 = b0 ? U[b0 - 1] : 0u;
        uint32_t lo1 = U[b0];
        bool nar0 = (U[b0] - lo0) <= (1u << 19);
        bool nar1 = (U[b1] - lo1) <= (1u << 19);
        if (s0 <= 16 && s1 <= 16 && nar0 && nar1) {
            const int half = lane >> 4, m = lane & 15;
            sort16_u32(buf, half ? g1 : g0, half ? s1 : s0,
                       half ? lo1 : lo0, m, si, s_top, s_bot);
        } else {
            if (s0 > 0) {
                if (nar0) {
                    if      (s0 <= 32)  sort_bucket_u32<1>(buf, g0, s0, lo0, lane, si, s_top, s_bot);
                    else if (s0 <= 64)  sort_bucket_u32<2>(buf, g0, s0, lo0, lane, si, s_top, s_bot);
                    else if (s0 <= 128) sort_bucket_u32<4>(buf, g0, s0, lo0, lane, si, s_top, s_bot);
                    else goto fb0;
                } else {
                    if      (s0 <= 32)  sort_bucket_u64<1>(buf, g0, s0, lane, si, s_top, s_bot);
                    else if (s0 <= 64)  sort_bucket_u64<2>(buf, g0, s0, lane, si, s_top, s_bot);
                    else if (s0 <= 128) sort_bucket_u64<4>(buf, g0, s0, lane, si, s_top, s_bot);
                    else {
                    fb0:  // unconditional-correctness fallback (statistically unreachable)
                        for (int m = lane; m < s0; m += 32) {
                            unsigned long long p = buf[g0 + m];
                            int rank = 0;
                            for (int j = 0; j < s0; j++) rank += (buf[g0 + j] < p);
                            int gr = g0 + rank;
                            si[gr] = (float)(unsigned)(p & 8191u);
                            if (gr < G)           s_top[gr] = inv_kd((uint32_t)(p >> 13));
                            if (gr >= I_COLS - G) s_bot[gr - (I_COLS - G)] = inv_kd((uint32_t)(p >> 13));
                        }
                    }
                }
            }
            if (s1 > 0) {
                if (nar1) {
                    if      (s1 <= 32)  sort_bucket_u32<1>(buf, g1, s1, lo1, lane, si, s_top, s_bot);
                    else if (s1 <= 64)  sort_bucket_u32<2>(buf, g1, s1, lo1, lane, si, s_top, s_bot);
                    else if (s1 <= 128) sort_bucket_u32<4>(buf, g1, s1, lo1, lane, si, s_top, s_bot);
                    else goto fb1;
                } else {
                    if      (s1 <= 32)  sort_bucket_u64<1>(buf, g1, s1, lane, si, s_top, s_bot);
                    else if (s1 <= 64)  sort_bucket_u64<2>(buf, g1, s1, lane, si, s_top, s_bot);
                    else if (s1 <= 128) sort_bucket_u64<4>(buf, g1, s1, lane, si, s_top, s_bot);
                    else {
                    fb1:
                        for (int m = lane; m < s1; m += 32) {
                            unsigned long long p = buf[g1 + m];
                            int rank = 0;
                            for (int j = 0; j < s1; j++) rank += (buf[g1 + j] < p);
                            int gr = g1 + rank;
                            si[gr] = (float)(unsigned)(p & 8191u);
                            if (gr < G)           s_top[gr] = inv_kd((uint32_t)(p >> 13));
                            if (gr >= I_COLS - G) s_bot[gr - (I_COLS - G)] = inv_kd((uint32_t)(p >> 13));
                        }
                    }
                }
            }
        }
    }
    __syncthreads();

    // ---- softmaxes ----
    if (tid == 0) {
        float m = s_top[0];
        #pragma unroll
        for (int i = 1; i < G; i++) m = fmaxf(m, s_top[i]);
        float e[G], s = 0.0f;
        #pragma unroll
        for (int i = 0; i < G; i++) { e[i] = expf(s_top[i] - m); s += e[i]; }
        float inv = 1.0f / s;
        #pragma unroll
        for (int i = 0; i < G; i++) s_win[i] = e[i] * inv;

        float m2 = 1.0f - s_bot[0];
        #pragma unroll
        for (int i = 1; i < G; i++) m2 = fmaxf(m2, 1.0f - s_bot[i]);
        float e2[G], s2 = 0.0f;
        #pragma unroll
        for (int i = 0; i < G; i++) { e2[i] = expf((1.0f - s_bot[i]) - m2); s2 += e2[i]; }
        float inv2 = 1.0f / s2;
        #pragma unroll
        for (int i = 0; i < G; i++) s_los[i] = -e2[i] * inv2;
    }
    __syncthreads();

    if (tid < G)          bc[tid] = s_win[tid];
    else if (tid < 2 * G) bc[I_COLS - G + (tid - G)] = s_los[tid - G];
}

extern "C" void kernel_launch(void* const* d_in, const int* in_sizes, int n_in,
                              void* d_out, int out_size)
{
    (void)in_sizes; (void)n_in; (void)out_size;
    const float* x = (const float*)d_in[0];
    float* out = (float*)d_out;

    cudaFuncSetAttribute(portfolio_bucket_v5,
                         cudaFuncAttributeMaxDynamicSharedMemorySize,
                         (int)SMEM_BYTES);
    portfolio_bucket_v5<<<B_ROWS, BT, SMEM_BYTES>>>(x, out);
}